// round 2
// baseline (speedup 1.0000x reference)
#include <cuda_runtime.h>

#define NMAX 100000
#define EMAX 1600000

// ---------------- device scratch (static, no allocation) ----------------
__device__ __align__(16) int   g_deg[NMAX];      // degree incl. self-loop
__device__ __align__(16) float g_dis[NMAX];      // deg^-1/2
__device__ __align__(16) int   g_row[EMAX];      // int32 source
__device__ __align__(16) int   g_col[EMAX];      // int32 target
__device__ __align__(16) int   g_ptr[NMAX];      // CSR segment start (per target node)
__device__ __align__(16) int   g_cur[NMAX];      // fill cursor
__device__ __align__(16) int   g_src[EMAX];      // CSR adjacency: source ids grouped by target
__device__ int   g_total;                        // segment allocator
__device__ __align__(16) float g_hw[(size_t)NMAX * 128];   // h @ W (reused width-10 for layer 4)
__device__ __align__(16) float g_acc[(size_t)NMAX * 128];  // propagate result (width-10 layer 4)

// ---------------- f32x2 packed math helpers ----------------
__device__ __forceinline__ void ffma2(unsigned long long& d, unsigned long long a, unsigned long long b) {
    asm("fma.rn.f32x2 %0, %1, %2, %0;" : "+l"(d) : "l"(a), "l"(b));
}
__device__ __forceinline__ float2 unpack2(unsigned long long v) {
    float2 r; asm("mov.b64 {%0, %1}, %2;" : "=f"(r.x), "=f"(r.y) : "l"(v)); return r;
}

// ---------------- graph preprocessing ----------------
__global__ void k_init(int N) {
    int i = blockIdx.x * blockDim.x + threadIdx.x;
    if (i < N) g_deg[i] = 1;                     // self-loop
    if (i == 0) g_total = 0;
}

// edge_index is int32 (JAX default x64-disabled downgrades int64 -> int32)
__global__ void k_count(const int* __restrict__ ei, int E) {
    int e = blockIdx.x * blockDim.x + threadIdx.x;
    if (e >= E) return;
    int r = ei[e];
    int c = ei[(size_t)E + e];
    g_row[e] = r;
    g_col[e] = c;
    atomicAdd(&g_deg[c], 1);
}

// per-block scan + one global atomic => disjoint CSR segments (order irrelevant)
__global__ void k_alloc(int N) {
    __shared__ int s[256];
    __shared__ int base;
    int tid = threadIdx.x;
    int i = blockIdx.x * 256 + tid;
    int d = (i < N) ? g_deg[i] : 1;
    if (i < N) g_dis[i] = rsqrtf((float)d);      // d >= 1 always
    int cnt = d - 1;
    s[tid] = cnt;
    __syncthreads();
    #pragma unroll
    for (int off = 1; off < 256; off <<= 1) {
        int v = (tid >= off) ? s[tid - off] : 0;
        __syncthreads();
        s[tid] += v;
        __syncthreads();
    }
    if (tid == 255) base = atomicAdd(&g_total, s[255]);
    __syncthreads();
    if (i < N) {
        int p = base + s[tid] - cnt;
        g_ptr[i] = p;
        g_cur[i] = p;
    }
}

__global__ void k_fill(int E) {
    int e = blockIdx.x * blockDim.x + threadIdx.x;
    if (e >= E) return;
    int c = g_col[e];
    int p = atomicAdd(&g_cur[c], 1);
    g_src[p] = g_row[e];
}

// ---------------- GEMM: g_hw = A' @ W, A' = (mode? relu(g_acc + bias) : Aext) ----------------
// 64 rows x 128 cols per block, 256 threads, K chunked by 32, f32x2 packed FFMA.
__global__ void __launch_bounds__(256) gemm128(const float* __restrict__ Aext,
                                               const float* __restrict__ W,
                                               const float* __restrict__ bias,
                                               int mode, int N) {
    __shared__ __align__(16) float As[32 * 136];  // [k][2*row] duplicated for packed broadcast
    __shared__ __align__(16) float Ws[32 * 132];  // [k][col], pad 132
    const float* A = mode ? g_acc : Aext;
    int tid = threadIdx.x;
    int tx = tid & 15;        // col group: cols tx*8 .. tx*8+7
    int ty = tid >> 4;        // row group: rows ty*4 .. ty*4+3
    int row0 = blockIdx.x * 64;

    unsigned long long acc[4][4];
    #pragma unroll
    for (int r = 0; r < 4; ++r)
        #pragma unroll
        for (int q = 0; q < 4; ++q) acc[r][q] = 0ull;

    for (int kb = 0; kb < 4; ++kb) {
        // load A chunk: 64 rows x 32 k (2 float4 per thread), transpose+duplicate into smem
        #pragma unroll
        for (int j = 0; j < 2; ++j) {
            int f = tid + 256 * j;          // 0..511
            int r = f >> 3;                 // row 0..63
            int k4 = (f & 7) * 4;           // k offset 0,4,..28
            int grow = row0 + r;
            float4 v = make_float4(0.f, 0.f, 0.f, 0.f);
            if (grow < N) v = *(const float4*)&A[(size_t)grow * 128 + kb * 32 + k4];
            if (mode) {
                float4 b4 = *(const float4*)&bias[kb * 32 + k4];
                v.x = fmaxf(v.x + b4.x, 0.f);
                v.y = fmaxf(v.y + b4.y, 0.f);
                v.z = fmaxf(v.z + b4.z, 0.f);
                v.w = fmaxf(v.w + b4.w, 0.f);
            }
            int r2 = r * 2;
            As[(k4 + 0) * 136 + r2] = v.x; As[(k4 + 0) * 136 + r2 + 1] = v.x;
            As[(k4 + 1) * 136 + r2] = v.y; As[(k4 + 1) * 136 + r2 + 1] = v.y;
            As[(k4 + 2) * 136 + r2] = v.z; As[(k4 + 2) * 136 + r2 + 1] = v.z;
            As[(k4 + 3) * 136 + r2] = v.w; As[(k4 + 3) * 136 + r2 + 1] = v.w;
        }
        // load W chunk: 32 k x 128 cols (4 float4 per thread)
        #pragma unroll
        for (int j = 0; j < 4; ++j) {
            int f = tid + 256 * j;          // 0..1023
            int kw = f >> 5;                // 0..31
            int jw = (f & 31) * 4;          // 0..124
            float4 v = *(const float4*)&W[(size_t)(kb * 32 + kw) * 128 + jw];
            *(float4*)&Ws[kw * 132 + jw] = v;
        }
        __syncthreads();
        #pragma unroll
        for (int k = 0; k < 32; ++k) {
            ulonglong2 a01 = *(const ulonglong2*)&As[k * 136 + ty * 8];
            ulonglong2 a23 = *(const ulonglong2*)&As[k * 136 + ty * 8 + 4];
            ulonglong2 b0 = *(const ulonglong2*)&Ws[k * 132 + tx * 8];
            ulonglong2 b1 = *(const ulonglong2*)&Ws[k * 132 + tx * 8 + 4];
            ffma2(acc[0][0], a01.x, b0.x); ffma2(acc[0][1], a01.x, b0.y);
            ffma2(acc[0][2], a01.x, b1.x); ffma2(acc[0][3], a01.x, b1.y);
            ffma2(acc[1][0], a01.y, b0.x); ffma2(acc[1][1], a01.y, b0.y);
            ffma2(acc[1][2], a01.y, b1.x); ffma2(acc[1][3], a01.y, b1.y);
            ffma2(acc[2][0], a23.x, b0.x); ffma2(acc[2][1], a23.x, b0.y);
            ffma2(acc[2][2], a23.x, b1.x); ffma2(acc[2][3], a23.x, b1.y);
            ffma2(acc[3][0], a23.y, b0.x); ffma2(acc[3][1], a23.y, b0.y);
            ffma2(acc[3][2], a23.y, b1.x); ffma2(acc[3][3], a23.y, b1.y);
        }
        __syncthreads();
    }
    #pragma unroll
    for (int r = 0; r < 4; ++r) {
        int grow = row0 + ty * 4 + r;
        if (grow < N) {
            float2 p0 = unpack2(acc[r][0]), p1 = unpack2(acc[r][1]);
            float2 p2 = unpack2(acc[r][2]), p3 = unpack2(acc[r][3]);
            float4 o0 = make_float4(p0.x, p0.y, p1.x, p1.y);
            float4 o1 = make_float4(p2.x, p2.y, p3.x, p3.y);
            *(float4*)&g_hw[(size_t)grow * 128 + tx * 8] = o0;
            *(float4*)&g_hw[(size_t)grow * 128 + tx * 8 + 4] = o1;
        }
    }
}

// ---------------- SpMM width 128: acc[i] = dis[i]*(dis[i]*hw[i] + sum dis[s]*hw[s]) ----------------
__global__ void spmm128(int N) {
    int warp = (blockIdx.x * blockDim.x + threadIdx.x) >> 5;
    if (warp >= N) return;
    int lane = threadIdx.x & 31;
    float di = g_dis[warp];
    float4 v = *(const float4*)&g_hw[(size_t)warp * 128 + lane * 4];
    float4 s;
    s.x = v.x * di; s.y = v.y * di; s.z = v.z * di; s.w = v.w * di;   // self-loop term
    int beg = g_ptr[warp];
    int end = beg + g_deg[warp] - 1;
    for (int p = beg; p < end; ++p) {
        int src = __ldg(&g_src[p]);
        float ds = __ldg(&g_dis[src]);
        float4 w = *(const float4*)&g_hw[(size_t)src * 128 + lane * 4];
        s.x += w.x * ds; s.y += w.y * ds; s.z += w.z * ds; s.w += w.w * ds;
    }
    s.x *= di; s.y *= di; s.z *= di; s.w *= di;
    *(float4*)&g_acc[(size_t)warp * 128 + lane * 4] = s;
}

// ---------------- layer 4 GEMM: g_hw[n,0:10] = relu(g_acc[n]+b_h1) @ W_out ----------------
__global__ void gemm_out(const float* __restrict__ W, const float* __restrict__ bias, int N) {
    __shared__ float Ws[128 * 10];
    __shared__ float bs[128];
    int tid = threadIdx.x;
    for (int i = tid; i < 1280; i += 256) Ws[i] = W[i];
    if (tid < 128) bs[tid] = bias[tid];
    __syncthreads();
    int n = blockIdx.x * 256 + tid;
    if (n >= N) return;
    float s[10];
    #pragma unroll
    for (int c = 0; c < 10; ++c) s[c] = 0.f;
    const float* a = g_acc + (size_t)n * 128;
    #pragma unroll 4
    for (int k = 0; k < 128; k += 4) {
        float4 v = *(const float4*)&a[k];
        float a0 = fmaxf(v.x + bs[k + 0], 0.f);
        float a1 = fmaxf(v.y + bs[k + 1], 0.f);
        float a2 = fmaxf(v.z + bs[k + 2], 0.f);
        float a3 = fmaxf(v.w + bs[k + 3], 0.f);
        const float* w0 = &Ws[k * 10];
        #pragma unroll
        for (int c = 0; c < 10; ++c)
            s[c] += a0 * w0[c] + a1 * w0[10 + c] + a2 * w0[20 + c] + a3 * w0[30 + c];
    }
    float* o = g_hw + (size_t)n * 10;
    #pragma unroll
    for (int c = 0; c < 10; ++c) o[c] = s[c];
}

// ---------------- SpMM width 10: 3 edges per warp iteration ----------------
__global__ void spmm10(int N) {
    int warp = (blockIdx.x * blockDim.x + threadIdx.x) >> 5;
    if (warp >= N) return;
    int lane = threadIdx.x & 31;
    int grp = lane / 10;
    int c = lane - grp * 10;
    bool active = lane < 30;
    float di = g_dis[warp];
    float s = 0.f;
    if (active && grp == 0) s = g_hw[(size_t)warp * 10 + c] * di;   // self-loop term
    int beg = g_ptr[warp];
    int m = g_deg[warp] - 1;
    for (int p = 0; p < m; p += 3) {
        int e = p + grp;
        if (active && e < m) {
            int src = __ldg(&g_src[beg + e]);
            float ds = __ldg(&g_dis[src]);
            s += g_hw[(size_t)src * 10 + c] * ds;
        }
    }
    float s1 = __shfl_sync(0xffffffffu, s, lane + 10);
    float s2 = __shfl_sync(0xffffffffu, s, lane + 20);
    if (lane < 10) g_acc[(size_t)warp * 10 + lane] = (s + s1 + s2) * di;
}

// ---------------- mean pooling: one block per graph, binary search on sorted batch ----------------
__device__ __forceinline__ int lower_bound_i(const int* a, int n, int key) {
    int lo = 0, hi = n;
    while (lo < hi) {
        int mid = (lo + hi) >> 1;
        if (a[mid] < key) lo = mid + 1; else hi = mid;
    }
    return lo;
}

__global__ void pool(const int* __restrict__ batch, const float* __restrict__ b_out,
                     float* __restrict__ out, int N) {
    __shared__ float sred[128];
    int g = blockIdx.x;
    int t = threadIdx.x;
    int lo = lower_bound_i(batch, N, g);
    int hi = lower_bound_i(batch, N, g + 1);
    float s = 0.f;
    if (t < 120) {
        int c = t / 12, sl = t % 12;
        for (int i = lo + sl; i < hi; i += 12) s += g_acc[(size_t)i * 10 + c];
    }
    sred[t] = s;
    __syncthreads();
    if (t < 10) {
        float tot = 0.f;
        #pragma unroll
        for (int j = 0; j < 12; ++j) tot += sred[t * 12 + j];
        float cnt = (float)(hi - lo);
        out[g * 10 + t] = (tot + cnt * b_out[t]) / fmaxf(cnt, 1.f);
    }
}

// ---------------- launcher ----------------
extern "C" void kernel_launch(void* const* d_in, const int* in_sizes, int n_in,
                              void* d_out, int out_size) {
    const float* x      = (const float*)d_in[0];
    const int*   ei     = (const int*)d_in[1];      // int32 (JAX x64 disabled)
    const int*   batch  = (const int*)d_in[2];      // int32
    const float* W_init = (const float*)d_in[3];
    const float* b_init = (const float*)d_in[4];
    const float* W_h0   = (const float*)d_in[5];
    const float* b_h0   = (const float*)d_in[6];
    const float* W_h1   = (const float*)d_in[7];
    const float* b_h1   = (const float*)d_in[8];
    const float* W_out  = (const float*)d_in[9];
    const float* b_out  = (const float*)d_in[10];
    float* out = (float*)d_out;

    int N = in_sizes[0] / 128;
    int E = in_sizes[1] / 2;

    int nb = (N + 255) / 256;
    int eb = (E + 255) / 256;
    int gb = (N + 63) / 64;
    int sb = (N + 7) / 8;   // warp per node, 8 warps/block

    // graph preprocessing (per launch — deterministic pipeline)
    k_init<<<nb, 256>>>(N);
    k_count<<<eb, 256>>>(ei, E);
    k_alloc<<<nb, 256>>>(N);
    k_fill<<<eb, 256>>>(E);

    // layer 1: x @ W_init -> propagate
    gemm128<<<gb, 256>>>(x, W_init, b_init, 0, N);
    spmm128<<<sb, 256>>>(N);
    // layer 2: relu(acc + b_init) @ W_h0 -> propagate
    gemm128<<<gb, 256>>>(nullptr, W_h0, b_init, 1, N);
    spmm128<<<sb, 256>>>(N);
    // layer 3: relu(acc + b_h0) @ W_h1 -> propagate
    gemm128<<<gb, 256>>>(nullptr, W_h1, b_h0, 1, N);
    spmm128<<<sb, 256>>>(N);
    // layer 4: relu(acc + b_h1) @ W_out (width 10) -> propagate
    gemm_out<<<nb, 256>>>(W_out, b_h1, N);
    spmm10<<<sb, 256>>>(N);
    // global mean pool (+ b_out)
    pool<<<512, 128>>>(batch, b_out, out, N);
}

// round 3
// speedup vs baseline: 1.3184x; 1.3184x over previous
#include <cuda_runtime.h>

#define NMAX 100000
#define EMAX 1600000

// ---------------- device scratch (static, no allocation) ----------------
__device__ __align__(16) int   g_deg[NMAX];      // in-edge count (no self-loop)
__device__ __align__(16) float g_dis[NMAX];      // (deg+1)^-1/2
__device__ __align__(16) int   g_ptr[NMAX];      // CSR segment start (per target node)
__device__ __align__(16) int   g_cur[NMAX];      // fill cursor
__device__ __align__(16) int   g_src[EMAX];      // CSR adjacency: source ids grouped by target
__device__ int   g_total;                        // segment allocator
__device__ __align__(16) float g_hw[(size_t)NMAX * 128];   // h @ W (reused width-10 for layer 4)
__device__ __align__(16) float g_acc[(size_t)NMAX * 128];  // propagate result (width-10 layer 4)

// ---------------- f32x2 packed math helpers ----------------
__device__ __forceinline__ void ffma2(unsigned long long& d, unsigned long long a, unsigned long long b) {
    asm("fma.rn.f32x2 %0, %1, %2, %0;" : "+l"(d) : "l"(a), "l"(b));
}
__device__ __forceinline__ float2 unpack2(unsigned long long v) {
    float2 r; asm("mov.b64 {%0, %1}, %2;" : "=f"(r.x), "=f"(r.y) : "l"(v)); return r;
}
__device__ __forceinline__ unsigned long long dup2(float a) {
    unsigned long long d; asm("mov.b64 %0, {%1, %1};" : "=l"(d) : "f"(a)); return d;
}

// ---------------- graph preprocessing ----------------
// edge_index is int32 (JAX x64-disabled downgrades int64 -> int32)
__global__ void k_count(const int* __restrict__ ei, int E) {
    int e = blockIdx.x * blockDim.x + threadIdx.x;
    if (e == 0) g_total = 0;
    if (e >= E) return;
    atomicAdd(&g_deg[ei[(size_t)E + e]], 1);
}

// per-block scan + one global atomic => disjoint CSR segments (order irrelevant)
__global__ void k_alloc(int N) {
    __shared__ int s[256];
    __shared__ int base;
    int tid = threadIdx.x;
    int i = blockIdx.x * 256 + tid;
    int d = (i < N) ? g_deg[i] : 0;              // edge count
    if (i < N) g_dis[i] = rsqrtf((float)(d + 1)); // +1 self-loop
    s[tid] = d;
    __syncthreads();
    #pragma unroll
    for (int off = 1; off < 256; off <<= 1) {
        int v = (tid >= off) ? s[tid - off] : 0;
        __syncthreads();
        s[tid] += v;
        __syncthreads();
    }
    if (tid == 255) base = atomicAdd(&g_total, s[255]);
    __syncthreads();
    if (i < N) {
        int p = base + s[tid] - d;
        g_ptr[i] = p;
        g_cur[i] = p;
    }
}

__global__ void k_fill(const int* __restrict__ ei, int E) {
    int e = blockIdx.x * blockDim.x + threadIdx.x;
    if (e >= E) return;
    int r = ei[e];
    int c = ei[(size_t)E + e];
    int p = atomicAdd(&g_cur[c], 1);
    g_src[p] = r;
}

// ---------------- GEMM: g_hw = A' @ W, A' = (mode? relu(g_acc + bias) : Aext) ----------------
// 128 rows x 128 cols per block, 256 threads, 8x8 outputs/thread, f32x2 packed FFMA.
__global__ void __launch_bounds__(256, 2) gemm128(const float* __restrict__ Aext,
                                                  const float* __restrict__ W,
                                                  const float* __restrict__ bias,
                                                  int mode, int N) {
    __shared__ __align__(16) float As[128 * 36];  // [row][k] chunk, pad 36
    __shared__ __align__(16) float Ws[32 * 132];  // [k][col], pad 132
    const float* A = mode ? g_acc : Aext;
    int tid = threadIdx.x;
    int tx = tid & 15;        // col group: cols tx*8 .. tx*8+7
    int ty = tid >> 4;        // row group: rows ty*8 .. ty*8+7
    int row0 = blockIdx.x * 128;

    unsigned long long acc[8][4];
    #pragma unroll
    for (int r = 0; r < 8; ++r)
        #pragma unroll
        for (int q = 0; q < 4; ++q) acc[r][q] = 0ull;

    for (int kb = 0; kb < 4; ++kb) {
        // load A chunk: 128 rows x 32 k (4 float4 per thread), row-major into smem
        #pragma unroll
        for (int j = 0; j < 4; ++j) {
            int f = tid + 256 * j;          // 0..1023
            int r = f >> 3;                 // row 0..127
            int k4 = (f & 7) * 4;           // k offset 0,4,..28
            int grow = row0 + r;
            float4 v = make_float4(0.f, 0.f, 0.f, 0.f);
            if (grow < N) v = *(const float4*)&A[(size_t)grow * 128 + kb * 32 + k4];
            if (mode) {
                float4 b4 = *(const float4*)&bias[kb * 32 + k4];
                v.x = fmaxf(v.x + b4.x, 0.f);
                v.y = fmaxf(v.y + b4.y, 0.f);
                v.z = fmaxf(v.z + b4.z, 0.f);
                v.w = fmaxf(v.w + b4.w, 0.f);
            }
            *(float4*)&As[r * 36 + k4] = v;
        }
        // load W chunk: 32 k x 128 cols (4 float4 per thread)
        #pragma unroll
        for (int j = 0; j < 4; ++j) {
            int f = tid + 256 * j;          // 0..1023
            int kw = f >> 5;                // 0..31
            int jw = (f & 31) * 4;          // 0..124
            *(float4*)&Ws[kw * 132 + jw] = *(const float4*)&W[(size_t)(kb * 32 + kw) * 128 + jw];
        }
        __syncthreads();
        #pragma unroll
        for (int kg = 0; kg < 8; ++kg) {
            float a[8][4];
            #pragma unroll
            for (int r = 0; r < 8; ++r)
                *(float4*)&a[r][0] = *(const float4*)&As[(ty * 8 + r) * 36 + kg * 4];
            #pragma unroll
            for (int kk = 0; kk < 4; ++kk) {
                int k = kg * 4 + kk;
                ulonglong2 b0 = *(const ulonglong2*)&Ws[k * 132 + tx * 8];
                ulonglong2 b1 = *(const ulonglong2*)&Ws[k * 132 + tx * 8 + 4];
                #pragma unroll
                for (int r = 0; r < 8; ++r) {
                    unsigned long long ap = dup2(a[r][kk]);
                    ffma2(acc[r][0], ap, b0.x);
                    ffma2(acc[r][1], ap, b0.y);
                    ffma2(acc[r][2], ap, b1.x);
                    ffma2(acc[r][3], ap, b1.y);
                }
            }
        }
        __syncthreads();
    }
    #pragma unroll
    for (int r = 0; r < 8; ++r) {
        int grow = row0 + ty * 8 + r;
        if (grow < N) {
            float2 p0 = unpack2(acc[r][0]), p1 = unpack2(acc[r][1]);
            float2 p2 = unpack2(acc[r][2]), p3 = unpack2(acc[r][3]);
            float4 o0 = make_float4(p0.x, p0.y, p1.x, p1.y);
            float4 o1 = make_float4(p2.x, p2.y, p3.x, p3.y);
            *(float4*)&g_hw[(size_t)grow * 128 + tx * 8] = o0;
            *(float4*)&g_hw[(size_t)grow * 128 + tx * 8 + 4] = o1;
        }
    }
}

// ---------------- SpMM width 128: acc[i] = dis[i]*(dis[i]*hw[i] + sum dis[s]*hw[s]) ----------------
__global__ void spmm128(int N) {
    int warp = (blockIdx.x * blockDim.x + threadIdx.x) >> 5;
    if (warp >= N) return;
    int lane = threadIdx.x & 31;
    float di = g_dis[warp];
    float4 v = *(const float4*)&g_hw[(size_t)warp * 128 + lane * 4];
    float4 s;
    s.x = v.x * di; s.y = v.y * di; s.z = v.z * di; s.w = v.w * di;   // self-loop term
    int beg = g_ptr[warp];
    int end = beg + g_deg[warp];
    int p = beg;
    // unroll by 2 for MLP on the 512B row gathers
    for (; p + 1 < end; p += 2) {
        int s0 = __ldg(&g_src[p]);
        int s1 = __ldg(&g_src[p + 1]);
        float d0 = __ldg(&g_dis[s0]);
        float d1 = __ldg(&g_dis[s1]);
        float4 w0 = *(const float4*)&g_hw[(size_t)s0 * 128 + lane * 4];
        float4 w1 = *(const float4*)&g_hw[(size_t)s1 * 128 + lane * 4];
        s.x += w0.x * d0; s.y += w0.y * d0; s.z += w0.z * d0; s.w += w0.w * d0;
        s.x += w1.x * d1; s.y += w1.y * d1; s.z += w1.z * d1; s.w += w1.w * d1;
    }
    if (p < end) {
        int s0 = __ldg(&g_src[p]);
        float d0 = __ldg(&g_dis[s0]);
        float4 w0 = *(const float4*)&g_hw[(size_t)s0 * 128 + lane * 4];
        s.x += w0.x * d0; s.y += w0.y * d0; s.z += w0.z * d0; s.w += w0.w * d0;
    }
    s.x *= di; s.y *= di; s.z *= di; s.w *= di;
    *(float4*)&g_acc[(size_t)warp * 128 + lane * 4] = s;
}

// ---------------- layer 4 GEMM: g_hw[n,0:10] = relu(g_acc[n]+b_h1) @ W_out ----------------
__global__ void gemm_out(const float* __restrict__ W, const float* __restrict__ bias, int N) {
    __shared__ float Ws[128 * 10];
    __shared__ float bs[128];
    int tid = threadIdx.x;
    for (int i = tid; i < 1280; i += 256) Ws[i] = W[i];
    if (tid < 128) bs[tid] = bias[tid];
    __syncthreads();
    int n = blockIdx.x * 256 + tid;
    if (n >= N) return;
    float s[10];
    #pragma unroll
    for (int c = 0; c < 10; ++c) s[c] = 0.f;
    const float* a = g_acc + (size_t)n * 128;
    #pragma unroll 4
    for (int k = 0; k < 128; k += 4) {
        float4 v = *(const float4*)&a[k];
        float a0 = fmaxf(v.x + bs[k + 0], 0.f);
        float a1 = fmaxf(v.y + bs[k + 1], 0.f);
        float a2 = fmaxf(v.z + bs[k + 2], 0.f);
        float a3 = fmaxf(v.w + bs[k + 3], 0.f);
        const float* w0 = &Ws[k * 10];
        #pragma unroll
        for (int c = 0; c < 10; ++c)
            s[c] += a0 * w0[c] + a1 * w0[10 + c] + a2 * w0[20 + c] + a3 * w0[30 + c];
    }
    float* o = g_hw + (size_t)n * 10;
    #pragma unroll
    for (int c = 0; c < 10; ++c) o[c] = s[c];
}

// ---------------- SpMM width 10: 3 edges per warp iteration ----------------
__global__ void spmm10(int N) {
    int warp = (blockIdx.x * blockDim.x + threadIdx.x) >> 5;
    if (warp >= N) return;
    int lane = threadIdx.x & 31;
    int grp = lane / 10;
    int c = lane - grp * 10;
    bool active = lane < 30;
    float di = g_dis[warp];
    float s = 0.f;
    if (active && grp == 0) s = g_hw[(size_t)warp * 10 + c] * di;   // self-loop term
    int beg = g_ptr[warp];
    int m = g_deg[warp];
    for (int p = 0; p < m; p += 3) {
        int e = p + grp;
        if (active && e < m) {
            int src = __ldg(&g_src[beg + e]);
            float ds = __ldg(&g_dis[src]);
            s += g_hw[(size_t)src * 10 + c] * ds;
        }
    }
    float s1 = __shfl_sync(0xffffffffu, s, lane + 10);
    float s2 = __shfl_sync(0xffffffffu, s, lane + 20);
    if (lane < 10) g_acc[(size_t)warp * 10 + lane] = (s + s1 + s2) * di;
}

// ---------------- mean pooling: one block per graph, binary search on sorted batch ----------------
__device__ __forceinline__ int lower_bound_i(const int* a, int n, int key) {
    int lo = 0, hi = n;
    while (lo < hi) {
        int mid = (lo + hi) >> 1;
        if (a[mid] < key) lo = mid + 1; else hi = mid;
    }
    return lo;
}

__global__ void pool(const int* __restrict__ batch, const float* __restrict__ b_out,
                     float* __restrict__ out, int N) {
    __shared__ float sred[128];
    int g = blockIdx.x;
    int t = threadIdx.x;
    int lo = lower_bound_i(batch, N, g);
    int hi = lower_bound_i(batch, N, g + 1);
    float s = 0.f;
    if (t < 120) {
        int c = t / 12, sl = t % 12;
        for (int i = lo + sl; i < hi; i += 12) s += g_acc[(size_t)i * 10 + c];
    }
    sred[t] = s;
    __syncthreads();
    if (t < 10) {
        float tot = 0.f;
        #pragma unroll
        for (int j = 0; j < 12; ++j) tot += sred[t * 12 + j];
        float cnt = (float)(hi - lo);
        out[g * 10 + t] = (tot + cnt * b_out[t]) / fmaxf(cnt, 1.f);
    }
}

// ---------------- launcher ----------------
extern "C" void kernel_launch(void* const* d_in, const int* in_sizes, int n_in,
                              void* d_out, int out_size) {
    const float* x      = (const float*)d_in[0];
    const int*   ei     = (const int*)d_in[1];      // int32 (JAX x64 disabled)
    const int*   batch  = (const int*)d_in[2];      // int32
    const float* W_init = (const float*)d_in[3];
    const float* b_init = (const float*)d_in[4];
    const float* W_h0   = (const float*)d_in[5];
    const float* b_h0   = (const float*)d_in[6];
    const float* W_h1   = (const float*)d_in[7];
    const float* b_h1   = (const float*)d_in[8];
    const float* W_out  = (const float*)d_in[9];
    const float* b_out  = (const float*)d_in[10];
    float* out = (float*)d_out;

    int N = in_sizes[0] / 128;
    int E = in_sizes[1] / 2;

    int nb = (N + 255) / 256;
    int eb = (E + 255) / 256;
    int gb = (N + 127) / 128;
    int sb = (N + 7) / 8;   // warp per node, 8 warps/block

    static int* deg_ptr = nullptr;
    if (!deg_ptr) cudaGetSymbolAddress((void**)&deg_ptr, g_deg);

    // graph preprocessing (per launch — deterministic pipeline)
    cudaMemsetAsync(deg_ptr, 0, (size_t)N * sizeof(int));
    k_count<<<eb, 256>>>(ei, E);
    k_alloc<<<nb, 256>>>(N);
    k_fill<<<eb, 256>>>(ei, E);

    // layer 1: x @ W_init -> propagate
    gemm128<<<gb, 256>>>(x, W_init, b_init, 0, N);
    spmm128<<<sb, 256>>>(N);
    // layer 2: relu(acc + b_init) @ W_h0 -> propagate
    gemm128<<<gb, 256>>>(nullptr, W_h0, b_init, 1, N);
    spmm128<<<sb, 256>>>(N);
    // layer 3: relu(acc + b_h0) @ W_h1 -> propagate
    gemm128<<<gb, 256>>>(nullptr, W_h1, b_h0, 1, N);
    spmm128<<<sb, 256>>>(N);
    // layer 4: relu(acc + b_h1) @ W_out (width 10) -> propagate
    gemm_out<<<nb, 256>>>(W_out, b_h1, N);
    spmm10<<<sb, 256>>>(N);
    // global mean pool (+ b_out)
    pool<<<512, 128>>>(batch, b_out, out, N);
}

// round 4
// speedup vs baseline: 1.8249x; 1.3842x over previous
#include <cuda_runtime.h>

#define NMAX 100000
#define EMAX 1600000

// ---------------- device scratch (static, no allocation) ----------------
__device__ __align__(16) int   g_deg[NMAX];      // in-edge count (no self-loop)
__device__ __align__(16) float g_dis[NMAX];      // (deg+1)^-1/2
__device__ __align__(16) int   g_ptr[NMAX];      // CSR segment start (per target node)
__device__ __align__(16) int   g_cur[NMAX];      // fill cursor
__device__ __align__(16) int   g_src[EMAX];      // CSR adjacency: source ids grouped by target
__device__ int   g_total;                        // segment allocator
__device__ __align__(16) float g_hw[(size_t)NMAX * 128];   // h @ W (reused width-10 for layer 4)
__device__ __align__(16) float g_acc[(size_t)NMAX * 128];  // propagate result (width-10 layer 4)

// ---------------- helpers ----------------
__device__ __forceinline__ float tf32r(float v) {
    unsigned r; asm("cvt.rna.tf32.f32 %0, %1;" : "=r"(r) : "f"(v));
    return __uint_as_float(r);
}
__device__ __forceinline__ void mma_tf32(float* c, const unsigned* a, const unsigned* b) {
    asm("mma.sync.aligned.m16n8k8.row.col.f32.tf32.tf32.f32 "
        "{%0,%1,%2,%3}, {%4,%5,%6,%7}, {%8,%9}, {%0,%1,%2,%3};"
        : "+f"(c[0]), "+f"(c[1]), "+f"(c[2]), "+f"(c[3])
        : "r"(a[0]), "r"(a[1]), "r"(a[2]), "r"(a[3]), "r"(b[0]), "r"(b[1]));
}

// ---------------- graph preprocessing ----------------
// edge_index is int32 (JAX x64-disabled downgrades int64 -> int32)
__global__ void k_count(const int* __restrict__ ei, int E) {
    int e = blockIdx.x * blockDim.x + threadIdx.x;
    if (e == 0) g_total = 0;
    if (e >= E) return;
    atomicAdd(&g_deg[ei[(size_t)E + e]], 1);
}

// per-block scan + one global atomic => disjoint CSR segments (order irrelevant)
__global__ void k_alloc(int N) {
    __shared__ int s[256];
    __shared__ int base;
    int tid = threadIdx.x;
    int i = blockIdx.x * 256 + tid;
    int d = (i < N) ? g_deg[i] : 0;              // edge count
    if (i < N) g_dis[i] = rsqrtf((float)(d + 1)); // +1 self-loop
    s[tid] = d;
    __syncthreads();
    #pragma unroll
    for (int off = 1; off < 256; off <<= 1) {
        int v = (tid >= off) ? s[tid - off] : 0;
        __syncthreads();
        s[tid] += v;
        __syncthreads();
    }
    if (tid == 255) base = atomicAdd(&g_total, s[255]);
    __syncthreads();
    if (i < N) {
        int p = base + s[tid] - d;
        g_ptr[i] = p;
        g_cur[i] = p;
    }
}

__global__ void k_fill(const int* __restrict__ ei, int E) {
    int e = blockIdx.x * blockDim.x + threadIdx.x;
    if (e >= E) return;
    int r = ei[e];
    int c = ei[(size_t)E + e];
    int p = atomicAdd(&g_cur[c], 1);
    g_src[p] = r;
}

// ---------------- tf32 tensor-core GEMM: g_hw = A' @ W ----------------
// A' = (mode ? relu(g_acc + bias) : Aext).  128x128 block tile, 8 warps of 32x64.
// W (tf32) fully resident in smem [k][n] stride 132; A chunk [m][k] stride 36.
#define WS_STRIDE 132
#define AS_STRIDE 36
#define SMEM_W_ELEMS (128 * WS_STRIDE)
#define SMEM_A_ELEMS (128 * AS_STRIDE)
#define GEMM_SMEM_BYTES ((SMEM_W_ELEMS + SMEM_A_ELEMS) * 4)

__global__ void __launch_bounds__(256, 2) gemm128(const float* __restrict__ Aext,
                                                  const float* __restrict__ W,
                                                  const float* __restrict__ bias,
                                                  int mode, int N) {
    extern __shared__ float smem[];
    float* Ws = smem;                    // [k 0..127][n 0..127] stride 132
    float* As = smem + SMEM_W_ELEMS;     // [m 0..127][k 0..31]  stride 36
    const float* A = mode ? g_acc : Aext;

    int tid  = threadIdx.x;
    int wid  = tid >> 5;
    int lane = tid & 31;
    int lr = lane >> 2;                  // 0..7
    int lc = lane & 3;                   // 0..3
    int warp_m = (wid & 3) * 32;         // 0,32,64,96
    int warp_n = (wid >> 2) * 64;        // 0,64
    int row0 = blockIdx.x * 128;

    // stage W once (cvt to tf32)
    #pragma unroll
    for (int i = tid * 4; i < 128 * 128; i += 1024) {
        float4 v = *(const float4*)&W[i];
        v.x = tf32r(v.x); v.y = tf32r(v.y); v.z = tf32r(v.z); v.w = tf32r(v.w);
        int r = i >> 7, c = i & 127;
        *(float4*)&Ws[r * WS_STRIDE + c] = v;
    }

    float acc[2][8][4];
    #pragma unroll
    for (int i = 0; i < 2; ++i)
        #pragma unroll
        for (int j = 0; j < 8; ++j)
            #pragma unroll
            for (int q = 0; q < 4; ++q) acc[i][j][q] = 0.f;

    for (int kb = 0; kb < 4; ++kb) {
        // stage A chunk: 128 rows x 32 k (4 float4/thread), bias+relu+tf32
        #pragma unroll
        for (int j = 0; j < 4; ++j) {
            int f = tid + 256 * j;          // 0..1023
            int r = f >> 3;                 // row 0..127
            int k4 = (f & 7) * 4;           // k offset 0,4,..28
            int grow = row0 + r;
            float4 v = make_float4(0.f, 0.f, 0.f, 0.f);
            if (grow < N) v = *(const float4*)&A[(size_t)grow * 128 + kb * 32 + k4];
            if (mode) {
                float4 b4 = *(const float4*)&bias[kb * 32 + k4];
                v.x = fmaxf(v.x + b4.x, 0.f);
                v.y = fmaxf(v.y + b4.y, 0.f);
                v.z = fmaxf(v.z + b4.z, 0.f);
                v.w = fmaxf(v.w + b4.w, 0.f);
            }
            v.x = tf32r(v.x); v.y = tf32r(v.y); v.z = tf32r(v.z); v.w = tf32r(v.w);
            *(float4*)&As[r * AS_STRIDE + k4] = v;
        }
        __syncthreads();

        #pragma unroll
        for (int ks = 0; ks < 4; ++ks) {
            int k0 = kb * 32 + ks * 8;
            // A fragments: 2 m-atoms of 16 rows
            unsigned af[2][4];
            #pragma unroll
            for (int i = 0; i < 2; ++i) {
                const float* ab = &As[(warp_m + i * 16 + lr) * AS_STRIDE + ks * 8 + lc];
                af[i][0] = __float_as_uint(ab[0]);
                af[i][1] = __float_as_uint(ab[8 * AS_STRIDE]);
                af[i][2] = __float_as_uint(ab[4]);
                af[i][3] = __float_as_uint(ab[8 * AS_STRIDE + 4]);
            }
            // B fragments: 8 n-atoms of 8 cols
            unsigned bf[8][2];
            #pragma unroll
            for (int j = 0; j < 8; ++j) {
                const float* bb = &Ws[(k0 + lc) * WS_STRIDE + warp_n + j * 8 + lr];
                bf[j][0] = __float_as_uint(bb[0]);
                bf[j][1] = __float_as_uint(bb[4 * WS_STRIDE]);
            }
            #pragma unroll
            for (int i = 0; i < 2; ++i)
                #pragma unroll
                for (int j = 0; j < 8; ++j)
                    mma_tf32(acc[i][j], af[i], bf[j]);
        }
        __syncthreads();
    }

    // epilogue: c0,c1 contiguous -> float2 stores
    #pragma unroll
    for (int i = 0; i < 2; ++i) {
        int rbase = row0 + warp_m + i * 16 + lr;
        #pragma unroll
        for (int j = 0; j < 8; ++j) {
            int col = warp_n + j * 8 + lc * 2;
            if (rbase < N)
                *(float2*)&g_hw[(size_t)rbase * 128 + col] = make_float2(acc[i][j][0], acc[i][j][1]);
            if (rbase + 8 < N)
                *(float2*)&g_hw[(size_t)(rbase + 8) * 128 + col] = make_float2(acc[i][j][2], acc[i][j][3]);
        }
    }
}

// ---------------- SpMM width 128: acc[i] = dis[i]*(dis[i]*hw[i] + sum dis[s]*hw[s]) ----------------
__global__ void spmm128(int N) {
    int warp = (blockIdx.x * blockDim.x + threadIdx.x) >> 5;
    if (warp >= N) return;
    int lane = threadIdx.x & 31;
    float di = g_dis[warp];
    float4 v = *(const float4*)&g_hw[(size_t)warp * 128 + lane * 4];
    float4 s;
    s.x = v.x * di; s.y = v.y * di; s.z = v.z * di; s.w = v.w * di;   // self-loop term
    int beg = g_ptr[warp];
    int end = beg + g_deg[warp];
    int p = beg;
    for (; p + 1 < end; p += 2) {
        int s0 = __ldg(&g_src[p]);
        int s1 = __ldg(&g_src[p + 1]);
        float d0 = __ldg(&g_dis[s0]);
        float d1 = __ldg(&g_dis[s1]);
        float4 w0 = *(const float4*)&g_hw[(size_t)s0 * 128 + lane * 4];
        float4 w1 = *(const float4*)&g_hw[(size_t)s1 * 128 + lane * 4];
        s.x += w0.x * d0; s.y += w0.y * d0; s.z += w0.z * d0; s.w += w0.w * d0;
        s.x += w1.x * d1; s.y += w1.y * d1; s.z += w1.z * d1; s.w += w1.w * d1;
    }
    if (p < end) {
        int s0 = __ldg(&g_src[p]);
        float d0 = __ldg(&g_dis[s0]);
        float4 w0 = *(const float4*)&g_hw[(size_t)s0 * 128 + lane * 4];
        s.x += w0.x * d0; s.y += w0.y * d0; s.z += w0.z * d0; s.w += w0.w * d0;
    }
    s.x *= di; s.y *= di; s.z *= di; s.w *= di;
    *(float4*)&g_acc[(size_t)warp * 128 + lane * 4] = s;
}

// ---------------- layer 4 GEMM: g_hw[n,0:10] = relu(g_acc[n]+b_h1) @ W_out ----------------
__global__ void gemm_out(const float* __restrict__ W, const float* __restrict__ bias, int N) {
    __shared__ float Ws[128 * 10];
    __shared__ float bs[128];
    int tid = threadIdx.x;
    for (int i = tid; i < 1280; i += 256) Ws[i] = W[i];
    if (tid < 128) bs[tid] = bias[tid];
    __syncthreads();
    int n = blockIdx.x * 256 + tid;
    if (n >= N) return;
    float s[10];
    #pragma unroll
    for (int c = 0; c < 10; ++c) s[c] = 0.f;
    const float* a = g_acc + (size_t)n * 128;
    #pragma unroll 4
    for (int k = 0; k < 128; k += 4) {
        float4 v = *(const float4*)&a[k];
        float a0 = fmaxf(v.x + bs[k + 0], 0.f);
        float a1 = fmaxf(v.y + bs[k + 1], 0.f);
        float a2 = fmaxf(v.z + bs[k + 2], 0.f);
        float a3 = fmaxf(v.w + bs[k + 3], 0.f);
        const float* w0 = &Ws[k * 10];
        #pragma unroll
        for (int c = 0; c < 10; ++c)
            s[c] += a0 * w0[c] + a1 * w0[10 + c] + a2 * w0[20 + c] + a3 * w0[30 + c];
    }
    float* o = g_hw + (size_t)n * 10;
    #pragma unroll
    for (int c = 0; c < 10; ++c) o[c] = s[c];
}

// ---------------- SpMM width 10: 3 edges per warp iteration ----------------
__global__ void spmm10(int N) {
    int warp = (blockIdx.x * blockDim.x + threadIdx.x) >> 5;
    if (warp >= N) return;
    int lane = threadIdx.x & 31;
    int grp = lane / 10;
    int c = lane - grp * 10;
    bool active = lane < 30;
    float di = g_dis[warp];
    float s = 0.f;
    if (active && grp == 0) s = g_hw[(size_t)warp * 10 + c] * di;   // self-loop term
    int beg = g_ptr[warp];
    int m = g_deg[warp];
    for (int p = 0; p < m; p += 3) {
        int e = p + grp;
        if (active && e < m) {
            int src = __ldg(&g_src[beg + e]);
            float ds = __ldg(&g_dis[src]);
            s += g_hw[(size_t)src * 10 + c] * ds;
        }
    }
    float s1 = __shfl_sync(0xffffffffu, s, lane + 10);
    float s2 = __shfl_sync(0xffffffffu, s, lane + 20);
    if (lane < 10) g_acc[(size_t)warp * 10 + lane] = (s + s1 + s2) * di;
}

// ---------------- mean pooling: one block per graph, binary search on sorted batch ----------------
__device__ __forceinline__ int lower_bound_i(const int* a, int n, int key) {
    int lo = 0, hi = n;
    while (lo < hi) {
        int mid = (lo + hi) >> 1;
        if (a[mid] < key) lo = mid + 1; else hi = mid;
    }
    return lo;
}

__global__ void pool(const int* __restrict__ batch, const float* __restrict__ b_out,
                     float* __restrict__ out, int N) {
    __shared__ float sred[128];
    int g = blockIdx.x;
    int t = threadIdx.x;
    int lo = lower_bound_i(batch, N, g);
    int hi = lower_bound_i(batch, N, g + 1);
    float s = 0.f;
    if (t < 120) {
        int c = t / 12, sl = t % 12;
        for (int i = lo + sl; i < hi; i += 12) s += g_acc[(size_t)i * 10 + c];
    }
    sred[t] = s;
    __syncthreads();
    if (t < 10) {
        float tot = 0.f;
        #pragma unroll
        for (int j = 0; j < 12; ++j) tot += sred[t * 12 + j];
        float cnt = (float)(hi - lo);
        out[g * 10 + t] = (tot + cnt * b_out[t]) / fmaxf(cnt, 1.f);
    }
}

// ---------------- launcher ----------------
extern "C" void kernel_launch(void* const* d_in, const int* in_sizes, int n_in,
                              void* d_out, int out_size) {
    const float* x      = (const float*)d_in[0];
    const int*   ei     = (const int*)d_in[1];      // int32 (JAX x64 disabled)
    const int*   batch  = (const int*)d_in[2];      // int32
    const float* W_init = (const float*)d_in[3];
    const float* b_init = (const float*)d_in[4];
    const float* W_h0   = (const float*)d_in[5];
    const float* b_h0   = (const float*)d_in[6];
    const float* W_h1   = (const float*)d_in[7];
    const float* b_h1   = (const float*)d_in[8];
    const float* W_out  = (const float*)d_in[9];
    const float* b_out  = (const float*)d_in[10];
    float* out = (float*)d_out;

    int N = in_sizes[0] / 128;
    int E = in_sizes[1] / 2;

    int nb = (N + 255) / 256;
    int eb = (E + 255) / 256;
    int gb = (N + 127) / 128;
    int sb = (N + 7) / 8;   // warp per node, 8 warps/block

    static int* deg_ptr = nullptr;
    if (!deg_ptr) {
        cudaGetSymbolAddress((void**)&deg_ptr, g_deg);
        cudaFuncSetAttribute(gemm128, cudaFuncAttributeMaxDynamicSharedMemorySize, GEMM_SMEM_BYTES);
    }

    // graph preprocessing (per launch — deterministic pipeline)
    cudaMemsetAsync(deg_ptr, 0, (size_t)N * sizeof(int));
    k_count<<<eb, 256>>>(ei, E);
    k_alloc<<<nb, 256>>>(N);
    k_fill<<<eb, 256>>>(ei, E);

    // layer 1: x @ W_init -> propagate
    gemm128<<<gb, 256, GEMM_SMEM_BYTES>>>(x, W_init, b_init, 0, N);
    spmm128<<<sb, 256>>>(N);
    // layer 2: relu(acc + b_init) @ W_h0 -> propagate
    gemm128<<<gb, 256, GEMM_SMEM_BYTES>>>(nullptr, W_h0, b_init, 1, N);
    spmm128<<<sb, 256>>>(N);
    // layer 3: relu(acc + b_h0) @ W_h1 -> propagate
    gemm128<<<gb, 256, GEMM_SMEM_BYTES>>>(nullptr, W_h1, b_h0, 1, N);
    spmm128<<<sb, 256>>>(N);
    // layer 4: relu(acc + b_h1) @ W_out (width 10) -> propagate
    gemm_out<<<nb, 256>>>(W_out, b_h1, N);
    spmm10<<<sb, 256>>>(N);
    // global mean pool (+ b_out)
    pool<<<512, 128>>>(batch, b_out, out, N);
}

// round 5
// speedup vs baseline: 2.1483x; 1.1772x over previous
#include <cuda_runtime.h>
#include <cuda_fp16.h>

#define NMAX 100000
#define EMAX 1600000

// ---------------- device scratch (static, no allocation) ----------------
__device__ __align__(16) int    g_deg[NMAX];     // in-edge count (no self-loop)
__device__ __align__(16) float  g_dis[NMAX];     // (deg+1)^-1/2
__device__ __align__(16) int    g_ptr[NMAX];     // CSR segment start (per target node)
__device__ __align__(16) int    g_cur[NMAX];     // fill cursor
__device__ __align__(16) int    g_src[EMAX];     // CSR adjacency: source ids grouped by target
__device__ int    g_total;                       // segment allocator
__device__ __align__(16) __half g_hwh[(size_t)NMAX * 128]; // dis-prefolded features (fp16)
__device__ __align__(16) float  g_h10[(size_t)NMAX * 10];  // width-10 prefolded features (fp32)
__device__ __align__(16) float  g_acc[(size_t)NMAX * 128]; // propagate result fp32 (width-10 L4)

// ---------------- helpers ----------------
__device__ __forceinline__ float tf32r(float v) {
    unsigned r; asm("cvt.rna.tf32.f32 %0, %1;" : "=r"(r) : "f"(v));
    return __uint_as_float(r);
}
__device__ __forceinline__ void mma_tf32(float* c, const unsigned* a, const unsigned* b) {
    asm("mma.sync.aligned.m16n8k8.row.col.f32.tf32.tf32.f32 "
        "{%0,%1,%2,%3}, {%4,%5,%6,%7}, {%8,%9}, {%0,%1,%2,%3};"
        : "+f"(c[0]), "+f"(c[1]), "+f"(c[2]), "+f"(c[3])
        : "r"(a[0]), "r"(a[1]), "r"(a[2]), "r"(a[3]), "r"(b[0]), "r"(b[1]));
}

// ---------------- graph preprocessing ----------------
__global__ void k_count(const int* __restrict__ ei, int E) {
    int e = blockIdx.x * blockDim.x + threadIdx.x;
    if (e == 0) g_total = 0;
    if (e >= E) return;
    atomicAdd(&g_deg[ei[(size_t)E + e]], 1);
}

__global__ void k_alloc(int N) {
    __shared__ int s[256];
    __shared__ int base;
    int tid = threadIdx.x;
    int i = blockIdx.x * 256 + tid;
    int d = (i < N) ? g_deg[i] : 0;
    if (i < N) g_dis[i] = rsqrtf((float)(d + 1));   // +1 self-loop
    s[tid] = d;
    __syncthreads();
    #pragma unroll
    for (int off = 1; off < 256; off <<= 1) {
        int v = (tid >= off) ? s[tid - off] : 0;
        __syncthreads();
        s[tid] += v;
        __syncthreads();
    }
    if (tid == 255) base = atomicAdd(&g_total, s[255]);
    __syncthreads();
    if (i < N) {
        int p = base + s[tid] - d;
        g_ptr[i] = p;
        g_cur[i] = p;
    }
}

__global__ void k_fill(const int* __restrict__ ei, int E) {
    int e = blockIdx.x * blockDim.x + threadIdx.x;
    if (e >= E) return;
    int r = ei[e];
    int c = ei[(size_t)E + e];
    int p = atomicAdd(&g_cur[c], 1);
    g_src[p] = r;
}

// ---------------- tf32 tensor-core GEMM: g_hwh = dis .* (A' @ W), fp16 out ----------------
// A' = (mode ? relu(g_acc + bias) : Aext).  128x128 block tile, 8 warps of 32x64.
#define WS_STRIDE 132
#define AS_STRIDE 36
#define SMEM_W_ELEMS (128 * WS_STRIDE)
#define SMEM_A_ELEMS (128 * AS_STRIDE)
#define GEMM_SMEM_BYTES ((SMEM_W_ELEMS + SMEM_A_ELEMS) * 4)

__global__ void __launch_bounds__(256, 2) gemm128(const float* __restrict__ Aext,
                                                  const float* __restrict__ W,
                                                  const float* __restrict__ bias,
                                                  int mode, int N) {
    extern __shared__ float smem[];
    float* Ws = smem;                    // [k][n] stride 132
    float* As = smem + SMEM_W_ELEMS;     // [m][k] stride 36
    const float* A = mode ? g_acc : Aext;

    int tid  = threadIdx.x;
    int wid  = tid >> 5;
    int lane = tid & 31;
    int lr = lane >> 2;                  // 0..7
    int lc = lane & 3;                   // 0..3
    int warp_m = (wid & 3) * 32;
    int warp_n = (wid >> 2) * 64;
    int row0 = blockIdx.x * 128;

    #pragma unroll
    for (int i = tid * 4; i < 128 * 128; i += 1024) {
        float4 v = *(const float4*)&W[i];
        v.x = tf32r(v.x); v.y = tf32r(v.y); v.z = tf32r(v.z); v.w = tf32r(v.w);
        int r = i >> 7, c = i & 127;
        *(float4*)&Ws[r * WS_STRIDE + c] = v;
    }

    float acc[2][8][4];
    #pragma unroll
    for (int i = 0; i < 2; ++i)
        #pragma unroll
        for (int j = 0; j < 8; ++j)
            #pragma unroll
            for (int q = 0; q < 4; ++q) acc[i][j][q] = 0.f;

    for (int kb = 0; kb < 4; ++kb) {
        #pragma unroll
        for (int j = 0; j < 4; ++j) {
            int f = tid + 256 * j;
            int r = f >> 3;
            int k4 = (f & 7) * 4;
            int grow = row0 + r;
            float4 v = make_float4(0.f, 0.f, 0.f, 0.f);
            if (grow < N) v = *(const float4*)&A[(size_t)grow * 128 + kb * 32 + k4];
            if (mode) {
                float4 b4 = *(const float4*)&bias[kb * 32 + k4];
                v.x = fmaxf(v.x + b4.x, 0.f);
                v.y = fmaxf(v.y + b4.y, 0.f);
                v.z = fmaxf(v.z + b4.z, 0.f);
                v.w = fmaxf(v.w + b4.w, 0.f);
            }
            v.x = tf32r(v.x); v.y = tf32r(v.y); v.z = tf32r(v.z); v.w = tf32r(v.w);
            *(float4*)&As[r * AS_STRIDE + k4] = v;
        }
        __syncthreads();

        #pragma unroll
        for (int ks = 0; ks < 4; ++ks) {
            unsigned af[2][4];
            #pragma unroll
            for (int i = 0; i < 2; ++i) {
                const float* ab = &As[(warp_m + i * 16 + lr) * AS_STRIDE + ks * 8 + lc];
                af[i][0] = __float_as_uint(ab[0]);
                af[i][1] = __float_as_uint(ab[8 * AS_STRIDE]);
                af[i][2] = __float_as_uint(ab[4]);
                af[i][3] = __float_as_uint(ab[8 * AS_STRIDE + 4]);
            }
            unsigned bf[8][2];
            #pragma unroll
            for (int j = 0; j < 8; ++j) {
                const float* bb = &Ws[(kb * 32 + ks * 8 + lc) * WS_STRIDE + warp_n + j * 8 + lr];
                bf[j][0] = __float_as_uint(bb[0]);
                bf[j][1] = __float_as_uint(bb[4 * WS_STRIDE]);
            }
            #pragma unroll
            for (int i = 0; i < 2; ++i)
                #pragma unroll
                for (int j = 0; j < 8; ++j)
                    mma_tf32(acc[i][j], af[i], bf[j]);
        }
        __syncthreads();
    }

    // epilogue: scale by dis[row], convert to half2, store
    #pragma unroll
    for (int i = 0; i < 2; ++i) {
        int r0i = row0 + warp_m + i * 16 + lr;
        int r1i = r0i + 8;
        float d0 = (r0i < N) ? g_dis[r0i] : 0.f;
        float d1 = (r1i < N) ? g_dis[r1i] : 0.f;
        #pragma unroll
        for (int j = 0; j < 8; ++j) {
            int col = warp_n + j * 8 + lc * 2;
            if (r0i < N)
                *(__half2*)&g_hwh[(size_t)r0i * 128 + col] =
                    __floats2half2_rn(acc[i][j][0] * d0, acc[i][j][1] * d0);
            if (r1i < N)
                *(__half2*)&g_hwh[(size_t)r1i * 128 + col] =
                    __floats2half2_rn(acc[i][j][2] * d1, acc[i][j][3] * d1);
        }
    }
}

// ---------------- SpMM width 128 (fp16 in, fp32 out) ----------------
// acc[i] = dis[i] * (hws[i] + sum_{s in N(i)} hws[s]),  hws prefolded with dis.
__device__ __forceinline__ void add_row(float4& s, const uint2* hp, size_t idx) {
    uint2 w = __ldg(&hp[idx]);
    float2 f0 = __half22float2(*(const __half2*)&w.x);
    float2 f1 = __half22float2(*(const __half2*)&w.y);
    s.x += f0.x; s.y += f0.y; s.z += f1.x; s.w += f1.y;
}

__global__ void spmm128(int N) {
    int warp = (blockIdx.x * blockDim.x + threadIdx.x) >> 5;
    if (warp >= N) return;
    int lane = threadIdx.x & 31;
    const uint2* hp = (const uint2*)g_hwh;       // 32 uint2 per row
    float4 s = make_float4(0.f, 0.f, 0.f, 0.f);
    add_row(s, hp, (size_t)warp * 32 + lane);    // self-loop term
    int beg = g_ptr[warp];
    int end = beg + g_deg[warp];
    int p = beg;
    for (; p + 3 < end; p += 4) {
        int s0 = __ldg(&g_src[p]);
        int s1 = __ldg(&g_src[p + 1]);
        int s2 = __ldg(&g_src[p + 2]);
        int s3 = __ldg(&g_src[p + 3]);
        add_row(s, hp, (size_t)s0 * 32 + lane);
        add_row(s, hp, (size_t)s1 * 32 + lane);
        add_row(s, hp, (size_t)s2 * 32 + lane);
        add_row(s, hp, (size_t)s3 * 32 + lane);
    }
    for (; p < end; ++p) {
        int s0 = __ldg(&g_src[p]);
        add_row(s, hp, (size_t)s0 * 32 + lane);
    }
    float di = g_dis[warp];
    s.x *= di; s.y *= di; s.z *= di; s.w *= di;
    *(float4*)&g_acc[(size_t)warp * 128 + lane * 4] = s;
}

// ---------------- layer 4 GEMM: g_h10[n] = dis[n] * (relu(g_acc[n]+b_h1) @ W_out) ----------------
__global__ void gemm_out(const float* __restrict__ W, const float* __restrict__ bias, int N) {
    __shared__ float Ws[128 * 10];
    __shared__ float bs[128];
    int tid = threadIdx.x;
    for (int i = tid; i < 1280; i += 256) Ws[i] = W[i];
    if (tid < 128) bs[tid] = bias[tid];
    __syncthreads();
    int n = blockIdx.x * 256 + tid;
    if (n >= N) return;
    float s[10];
    #pragma unroll
    for (int c = 0; c < 10; ++c) s[c] = 0.f;
    const float* a = g_acc + (size_t)n * 128;
    #pragma unroll 4
    for (int k = 0; k < 128; k += 4) {
        float4 v = *(const float4*)&a[k];
        float a0 = fmaxf(v.x + bs[k + 0], 0.f);
        float a1 = fmaxf(v.y + bs[k + 1], 0.f);
        float a2 = fmaxf(v.z + bs[k + 2], 0.f);
        float a3 = fmaxf(v.w + bs[k + 3], 0.f);
        const float* w0 = &Ws[k * 10];
        #pragma unroll
        for (int c = 0; c < 10; ++c)
            s[c] += a0 * w0[c] + a1 * w0[10 + c] + a2 * w0[20 + c] + a3 * w0[30 + c];
    }
    float dn = g_dis[n];
    float* o = g_h10 + (size_t)n * 10;
    #pragma unroll
    for (int c = 0; c < 10; ++c) o[c] = s[c] * dn;
}

// ---------------- SpMM width 10 (prefolded fp32) ----------------
__global__ void spmm10(int N) {
    int warp = (blockIdx.x * blockDim.x + threadIdx.x) >> 5;
    if (warp >= N) return;
    int lane = threadIdx.x & 31;
    int grp = lane / 10;
    int c = lane - grp * 10;
    bool active = lane < 30;
    float s = 0.f;
    if (active && grp == 0) s = g_h10[(size_t)warp * 10 + c];     // self-loop term
    int beg = g_ptr[warp];
    int m = g_deg[warp];
    for (int p = 0; p < m; p += 3) {
        int e = p + grp;
        if (active && e < m) {
            int src = __ldg(&g_src[beg + e]);
            s += g_h10[(size_t)src * 10 + c];
        }
    }
    float s1 = __shfl_sync(0xffffffffu, s, lane + 10);
    float s2 = __shfl_sync(0xffffffffu, s, lane + 20);
    if (lane < 10) g_acc[(size_t)warp * 10 + lane] = (s + s1 + s2) * g_dis[warp];
}

// ---------------- mean pooling ----------------
__device__ __forceinline__ int lower_bound_i(const int* a, int n, int key) {
    int lo = 0, hi = n;
    while (lo < hi) {
        int mid = (lo + hi) >> 1;
        if (a[mid] < key) lo = mid + 1; else hi = mid;
    }
    return lo;
}

__global__ void pool(const int* __restrict__ batch, const float* __restrict__ b_out,
                     float* __restrict__ out, int N) {
    __shared__ float sred[128];
    int g = blockIdx.x;
    int t = threadIdx.x;
    int lo = lower_bound_i(batch, N, g);
    int hi = lower_bound_i(batch, N, g + 1);
    float s = 0.f;
    if (t < 120) {
        int c = t / 12, sl = t % 12;
        for (int i = lo + sl; i < hi; i += 12) s += g_acc[(size_t)i * 10 + c];
    }
    sred[t] = s;
    __syncthreads();
    if (t < 10) {
        float tot = 0.f;
        #pragma unroll
        for (int j = 0; j < 12; ++j) tot += sred[t * 12 + j];
        float cnt = (float)(hi - lo);
        out[g * 10 + t] = (tot + cnt * b_out[t]) / fmaxf(cnt, 1.f);
    }
}

// ---------------- launcher ----------------
extern "C" void kernel_launch(void* const* d_in, const int* in_sizes, int n_in,
                              void* d_out, int out_size) {
    const float* x      = (const float*)d_in[0];
    const int*   ei     = (const int*)d_in[1];
    const int*   batch  = (const int*)d_in[2];
    const float* W_init = (const float*)d_in[3];
    const float* b_init = (const float*)d_in[4];
    const float* W_h0   = (const float*)d_in[5];
    const float* b_h0   = (const float*)d_in[6];
    const float* W_h1   = (const float*)d_in[7];
    const float* b_h1   = (const float*)d_in[8];
    const float* W_out  = (const float*)d_in[9];
    const float* b_out  = (const float*)d_in[10];
    float* out = (float*)d_out;

    int N = in_sizes[0] / 128;
    int E = in_sizes[1] / 2;

    int nb = (N + 255) / 256;
    int eb = (E + 255) / 256;
    int gb = (N + 127) / 128;
    int sb = (N + 7) / 8;

    static int* deg_ptr = nullptr;
    if (!deg_ptr) {
        cudaGetSymbolAddress((void**)&deg_ptr, g_deg);
        cudaFuncSetAttribute(gemm128, cudaFuncAttributeMaxDynamicSharedMemorySize, GEMM_SMEM_BYTES);
    }

    cudaMemsetAsync(deg_ptr, 0, (size_t)N * sizeof(int));
    k_count<<<eb, 256>>>(ei, E);
    k_alloc<<<nb, 256>>>(N);
    k_fill<<<eb, 256>>>(ei, E);

    gemm128<<<gb, 256, GEMM_SMEM_BYTES>>>(x, W_init, b_init, 0, N);
    spmm128<<<sb, 256>>>(N);
    gemm128<<<gb, 256, GEMM_SMEM_BYTES>>>(nullptr, W_h0, b_init, 1, N);
    spmm128<<<sb, 256>>>(N);
    gemm128<<<gb, 256, GEMM_SMEM_BYTES>>>(nullptr, W_h1, b_h0, 1, N);
    spmm128<<<sb, 256>>>(N);
    gemm_out<<<nb, 256>>>(W_out, b_h1, N);
    spmm10<<<sb, 256>>>(N);
    pool<<<512, 128>>>(batch, b_out, out, N);
}